// round 7
// baseline (speedup 1.0000x reference)
#include <cuda_runtime.h>
#include <cuda_fp16.h>

// Shape: [B=2, C=1, D=160, H=192, W=160] fp32, WIN=9 (radius 4), SAME zero pad.
#define Bn 2
#define Dn 160
#define Hn 192
#define Wn 160
#define NV (Bn*Dn*Hn*Wn)            // 9,830,400
#define RW 4
#define WSZ 729.0f

// Fused W+H pass tiling (4 blocks/SM @ 46.8 KB smem, 2 syncs total).
#define TH 8                         // output rows per block
#define ROWS (TH + 2*RW)             // 16 input rows with halo
#define ISTR 164                     // I/J smem stride (float4-aligned)
#define SSTRH 161                    // W-sum smem stride in halfs (odd)
#define SM_IJ (ROWS * ISTR)          // one input plane (floats)
#define SM_SH (ROWS * SSTRH)         // one W-sum plane (halfs)
#define SMEM_BYTES (2 * SM_IJ * 4 + 5 * SM_SH * 2)   // 46,752 B

// D-pass: 8 columns/thread (uint4 = 8 halfs), 8 D-segments (40% halo).
#define NCOLO (Bn*Hn*(Wn/8))         // 7,680 column-octets
#define DSEG 8
#define DSEGLEN (Dn/DSEG)            // 20
#define DPB ((NCOLO*DSEG)/256)       // 240 blocks

// Intermediate buffer in fp16, channel-major [c][b][d][h][w]. ~98.3 MB.
__device__ __align__(16) __half g_hbuf[5ll * NV];
__device__ float g_part[DPB];
__device__ unsigned g_cnt = 0;       // wraps -> graph-replay safe

// ---------------------------------------------------------------------------
// Fused W+H pass: stage I,J -> W window-sums (products on the fly, fp16
// scratch) -> H window-sum -> fp16 gmem.  256 threads/block, 7680 blocks.
// ---------------------------------------------------------------------------
__global__ void ncc_fused(const float* __restrict__ I, const float* __restrict__ J) {
    extern __shared__ char smraw[];
    float* __restrict__ sI = (float*)smraw;                  // [ROWS][ISTR]
    float* __restrict__ sJ = sI + SM_IJ;                     // [ROWS][ISTR]
    __half* __restrict__ sS = (__half*)(sJ + SM_IJ);         // [5][ROWS][SSTRH]

    const int t = threadIdx.x;
    const int tile = blockIdx.x;
    const int ht = tile % (Hn / TH);
    const int slice = tile / (Hn / TH);
    const int d = slice % Dn;
    const int b = slice / Dn;
    const int h0 = ht * TH;

    // Phase A: float4 loads of I,J rows [h0-4, h0+TH+4) into smem.
    for (int idx = t; idx < ROWS * (Wn / 4); idx += 256) {
        const int r = idx / (Wn / 4);
        const int wq = (idx - r * (Wn / 4)) * 4;
        const int hg = h0 - RW + r;
        float4 a = make_float4(0.f, 0.f, 0.f, 0.f);
        float4 c = a;
        if (hg >= 0 && hg < Hn) {
            const size_t o = ((size_t)(b * Dn + d) * Hn + hg) * Wn + wq;
            a = *(const float4*)(I + o);
            c = *(const float4*)(J + o);
        }
        *(float4*)(sI + r * ISTR + wq) = a;
        *(float4*)(sJ + r * ISTR + wq) = c;
    }
    __syncthreads();

    // Phase B: W window-sums for all 5 channels (products on the fly, fp32
    // running sums, fp16 stores). 16 rows x 16 chunks of 10 = 256 jobs.
    {
        const int row = t >> 4;
        const int c0 = (t & 15) * 10;
        const float* __restrict__ rI = sI + row * ISTR;
        const float* __restrict__ rJ = sJ + row * ISTR;
        float s0 = 0.f, s1 = 0.f, s2 = 0.f, s3 = 0.f, s4 = 0.f;
        #pragma unroll
        for (int k = c0 - RW; k <= c0 + RW; ++k) {
            if (k >= 0 && k < Wn) {
                const float a = rI[k], c = rJ[k];
                s0 += a; s1 += c; s2 += a * a; s3 += c * c; s4 += a * c;
            }
        }
        #pragma unroll
        for (int i = 0; i < 10; ++i) {
            const int w = c0 + i;
            sS[0 * SM_SH + row * SSTRH + w] = __float2half_rn(s0);
            sS[1 * SM_SH + row * SSTRH + w] = __float2half_rn(s1);
            sS[2 * SM_SH + row * SSTRH + w] = __float2half_rn(s2);
            sS[3 * SM_SH + row * SSTRH + w] = __float2half_rn(s3);
            sS[4 * SM_SH + row * SSTRH + w] = __float2half_rn(s4);
            if (w + RW + 1 < Wn) {
                const float a = rI[w + RW + 1], c = rJ[w + RW + 1];
                s0 += a; s1 += c; s2 += a * a; s3 += c * c; s4 += a * c;
            }
            if (w - RW >= 0) {
                const float a = rI[w - RW], c = rJ[w - RW];
                s0 -= a; s1 -= c; s2 -= a * a; s3 -= c * c; s4 -= a * c;
            }
        }
    }
    __syncthreads();

    // Phase C: H window-sum per (ch, w) column (fp32 running over fp16 taps).
    for (int job = t; job < 5 * Wn; job += 256) {
        const int w = job % Wn;
        const int ch = job / Wn;
        const __half* __restrict__ col = sS + ch * SM_SH + w;
        float s = 0.f;
        #pragma unroll
        for (int r = 0; r < 2 * RW; ++r) s += __half2float(col[r * SSTRH]);
        __half* __restrict__ ob = g_hbuf + (size_t)ch * NV +
                                  ((size_t)(b * Dn + d) * Hn + h0) * Wn + w;
        #pragma unroll
        for (int o = 0; o < TH; ++o) {
            s += __half2float(col[(o + 2 * RW) * SSTRH]);
            ob[(size_t)o * Wn] = __float2half_rn(s);
            s -= __half2float(col[o * SSTRH]);
        }
    }
}

// ---------------------------------------------------------------------------
// D-pass: running D window-sum (8 columns/thread via LDG.128) + cc +
// reduction + last-block finalize. 240 blocks x 256 threads, 8 segs of 20.
// ---------------------------------------------------------------------------
__device__ __forceinline__ void cvt8(uint4 v, float* __restrict__ f) {
    float2 p;
    p = __half22float2(*reinterpret_cast<__half2*>(&v.x)); f[0] = p.x; f[1] = p.y;
    p = __half22float2(*reinterpret_cast<__half2*>(&v.y)); f[2] = p.x; f[3] = p.y;
    p = __half22float2(*reinterpret_cast<__half2*>(&v.z)); f[4] = p.x; f[5] = p.y;
    p = __half22float2(*reinterpret_cast<__half2*>(&v.w)); f[6] = p.x; f[7] = p.y;
}

__global__ void ncc_dpass(float* __restrict__ outp) {
    const int tid = blockIdx.x * blockDim.x + threadIdx.x;   // < 61440
    const int seg = tid / NCOLO;
    const int cp = tid - seg * NCOLO;
    const int wo = cp % (Wn / 8);
    int r = cp / (Wn / 8);
    const int h = r % Hn;
    const int b = r / Hn;
    const int d0 = seg * DSEGLEN;

    const size_t dS = (size_t)Hn * (Wn / 8);                 // slice stride (uint4)
    const size_t base = ((size_t)b * Dn) * dS + (size_t)h * (Wn / 8) + wo;
    const uint4* __restrict__ in = (const uint4*)g_hbuf;
    const size_t cNV = (size_t)NV / 8;                       // channel stride (uint4)

    float s[5][8];
    #pragma unroll
    for (int c = 0; c < 5; ++c)
        #pragma unroll
        for (int l = 0; l < 8; ++l) s[c][l] = 0.f;

    #pragma unroll
    for (int d = d0 - RW; d < d0 + RW; ++d) {
        if (d >= 0) {
            const size_t o = base + (size_t)d * dS;
            #pragma unroll
            for (int c = 0; c < 5; ++c) {
                float f[8];
                cvt8(in[c * cNV + o], f);
                #pragma unroll
                for (int l = 0; l < 8; ++l) s[c][l] += f[l];
            }
        }
    }

    const float inv = 1.0f / WSZ;
    float acc = 0.f;
    for (int dout = d0; dout < d0 + DSEGLEN; ++dout) {
        if (dout + RW < Dn) {
            const size_t o = base + (size_t)(dout + RW) * dS;
            #pragma unroll
            for (int c = 0; c < 5; ++c) {
                float f[8];
                cvt8(in[c * cNV + o], f);
                #pragma unroll
                for (int l = 0; l < 8; ++l) s[c][l] += f[l];
            }
        }
        #pragma unroll
        for (int l = 0; l < 8; ++l) {
            const float uI = s[0][l] * inv, uJ = s[1][l] * inv;
            const float cross = s[4][l] - uJ * s[0][l] - uI * s[1][l] + uI * uJ * WSZ;
            const float Iv = s[2][l] - 2.f * uI * s[0][l] + uI * uI * WSZ;
            const float Jv = s[3][l] - 2.f * uJ * s[1][l] + uJ * uJ * WSZ;
            acc += cross * cross / (Iv * Jv + 1e-5f);
        }
        if (dout - RW >= 0) {
            const size_t o = base + (size_t)(dout - RW) * dS;
            #pragma unroll
            for (int c = 0; c < 5; ++c) {
                float f[8];
                cvt8(in[c * cNV + o], f);
                #pragma unroll
                for (int l = 0; l < 8; ++l) s[c][l] -= f[l];
            }
        }
    }

    __shared__ float red[256];
    red[threadIdx.x] = acc;
    __syncthreads();
    #pragma unroll
    for (int st = 128; st > 0; st >>= 1) {
        if (threadIdx.x < st) red[threadIdx.x] += red[threadIdx.x + st];
        __syncthreads();
    }

    __shared__ bool is_last;
    if (threadIdx.x == 0) {
        g_part[blockIdx.x] = red[0];
        __threadfence();
        unsigned old = atomicInc(&g_cnt, DPB - 1);
        is_last = (old == DPB - 1);
    }
    __syncthreads();

    if (is_last) {
        const volatile float* vp = g_part;
        double v = 0.0;
        for (int i = threadIdx.x; i < DPB; i += 256) v += (double)vp[i];
        __shared__ double dred[256];
        dred[threadIdx.x] = v;
        __syncthreads();
        #pragma unroll
        for (int st = 128; st > 0; st >>= 1) {
            if (threadIdx.x < st) dred[threadIdx.x] += dred[threadIdx.x + st];
            __syncthreads();
        }
        if (threadIdx.x == 0) outp[0] = (float)(-(dred[0] / (double)NV));
    }
}

extern "C" void kernel_launch(void* const* d_in, const int* in_sizes, int n_in,
                              void* d_out, int out_size) {
    const float* I = (const float*)d_in[0];
    const float* J = (const float*)d_in[1];
    float* out = (float*)d_out;

    cudaFuncSetAttribute(ncc_fused, cudaFuncAttributeMaxDynamicSharedMemorySize,
                         SMEM_BYTES);

    ncc_fused<<<Bn * Dn * (Hn / TH), 256, SMEM_BYTES>>>(I, J);  // 7680 blocks
    ncc_dpass<<<DPB, 256>>>(out);                                // 240 blocks
}

// round 8
// speedup vs baseline: 1.1630x; 1.1630x over previous
#include <cuda_runtime.h>
#include <cuda_fp16.h>

// Shape: [B=2, C=1, D=160, H=192, W=160] fp32, WIN=9 (radius 4), SAME zero pad.
#define Bn 2
#define Dn 160
#define Hn 192
#define Wn 160
#define NV (Bn*Dn*Hn*Wn)            // 9,830,400
#define RW 4
#define WSZ 729.0f

// Fused W+H pass tiling: TH=16, 384 threads, 3 blocks/SM @ 70.1 KB smem.
#define TH 16                        // output rows per block
#define ROWS (TH + 2*RW)             // 24 input rows with halo
#define ISTR 164                     // I/J smem stride (float4-aligned)
#define SSTRH 161                    // W-sum smem stride in halfs (odd)
#define SM_IJ (ROWS * ISTR)          // one input plane (floats)
#define SM_SH (ROWS * SSTRH)         // one W-sum plane (halfs)
#define SMEM_BYTES (2 * SM_IJ * 4 + 5 * SM_SH * 2)   // 70,128 B
#define FT 384                       // fused block threads

// D-pass: 4 columns/thread (uint2), 8 D-segments (40% halo), 128-thr blocks.
#define NCOLQ (Bn*Hn*(Wn/4))         // 15,360 column-quads
#define DSEG 8
#define DSEGLEN (Dn/DSEG)            // 20
#define DPB ((NCOLQ*DSEG)/128)       // 960 blocks

// Intermediate buffer in fp16, channel-major [c][b][d][h][w]. ~98.3 MB.
__device__ __align__(16) __half g_hbuf[5ll * NV];
__device__ float g_part[DPB];
__device__ unsigned g_cnt = 0;       // wraps -> graph-replay safe

// ---------------------------------------------------------------------------
// Fused W+H pass: stage I,J -> W window-sums (products on the fly, fp16
// scratch) -> H window-sum -> fp16 gmem.  384 threads/block, 3840 blocks.
// ---------------------------------------------------------------------------
__global__ __launch_bounds__(FT, 3)
void ncc_fused(const float* __restrict__ I, const float* __restrict__ J) {
    extern __shared__ char smraw[];
    float* __restrict__ sI = (float*)smraw;                  // [ROWS][ISTR]
    float* __restrict__ sJ = sI + SM_IJ;                     // [ROWS][ISTR]
    __half* __restrict__ sS = (__half*)(sJ + SM_IJ);         // [5][ROWS][SSTRH]

    const int t = threadIdx.x;
    const int tile = blockIdx.x;
    const int ht = tile % (Hn / TH);       // 12 tiles along H
    const int slice = tile / (Hn / TH);
    const int d = slice % Dn;
    const int b = slice / Dn;
    const int h0 = ht * TH;

    // Phase A: float4 loads of I,J rows [h0-4, h0+TH+4) into smem.
    for (int idx = t; idx < ROWS * (Wn / 4); idx += FT) {
        const int r = idx / (Wn / 4);
        const int wq = (idx - r * (Wn / 4)) * 4;
        const int hg = h0 - RW + r;
        float4 a = make_float4(0.f, 0.f, 0.f, 0.f);
        float4 c = a;
        if (hg >= 0 && hg < Hn) {
            const size_t o = ((size_t)(b * Dn + d) * Hn + hg) * Wn + wq;
            a = *(const float4*)(I + o);
            c = *(const float4*)(J + o);
        }
        *(float4*)(sI + r * ISTR + wq) = a;
        *(float4*)(sJ + r * ISTR + wq) = c;
    }
    __syncthreads();

    // Phase B: W window-sums for all 5 channels (products on the fly, fp32
    // running sums, fp16 stores). 24 rows x 16 chunks of 10 = 384 jobs.
    {
        const int row = t >> 4;
        const int c0 = (t & 15) * 10;
        const float* __restrict__ rI = sI + row * ISTR;
        const float* __restrict__ rJ = sJ + row * ISTR;
        float s0 = 0.f, s1 = 0.f, s2 = 0.f, s3 = 0.f, s4 = 0.f;
        #pragma unroll
        for (int k = c0 - RW; k <= c0 + RW; ++k) {
            if (k >= 0 && k < Wn) {
                const float a = rI[k], c = rJ[k];
                s0 += a; s1 += c; s2 += a * a; s3 += c * c; s4 += a * c;
            }
        }
        #pragma unroll
        for (int i = 0; i < 10; ++i) {
            const int w = c0 + i;
            sS[0 * SM_SH + row * SSTRH + w] = __float2half_rn(s0);
            sS[1 * SM_SH + row * SSTRH + w] = __float2half_rn(s1);
            sS[2 * SM_SH + row * SSTRH + w] = __float2half_rn(s2);
            sS[3 * SM_SH + row * SSTRH + w] = __float2half_rn(s3);
            sS[4 * SM_SH + row * SSTRH + w] = __float2half_rn(s4);
            if (w + RW + 1 < Wn) {
                const float a = rI[w + RW + 1], c = rJ[w + RW + 1];
                s0 += a; s1 += c; s2 += a * a; s3 += c * c; s4 += a * c;
            }
            if (w - RW >= 0) {
                const float a = rI[w - RW], c = rJ[w - RW];
                s0 -= a; s1 -= c; s2 -= a * a; s3 -= c * c; s4 -= a * c;
            }
        }
    }
    __syncthreads();

    // Phase C: H window-sum per (ch, w) column (fp32 running over fp16 taps).
    for (int job = t; job < 5 * Wn; job += FT) {
        const int w = job % Wn;
        const int ch = job / Wn;
        const __half* __restrict__ col = sS + ch * SM_SH + w;
        float s = 0.f;
        #pragma unroll
        for (int r = 0; r < 2 * RW; ++r) s += __half2float(col[r * SSTRH]);
        __half* __restrict__ ob = g_hbuf + (size_t)ch * NV +
                                  ((size_t)(b * Dn + d) * Hn + h0) * Wn + w;
        #pragma unroll
        for (int o = 0; o < TH; ++o) {
            s += __half2float(col[(o + 2 * RW) * SSTRH]);
            ob[(size_t)o * Wn] = __float2half_rn(s);
            s -= __half2float(col[o * SSTRH]);
        }
    }
}

// ---------------------------------------------------------------------------
// D-pass: running D window-sum (4 columns/thread via LDG.64) + cc +
// reduction + last-block finalize. 960 blocks x 128 threads, 8 segs of 20.
// ---------------------------------------------------------------------------
__device__ __forceinline__ float4 cvt4(uint2 v) {
    const float2 fa = __half22float2(*reinterpret_cast<__half2*>(&v.x));
    const float2 fb = __half22float2(*reinterpret_cast<__half2*>(&v.y));
    return make_float4(fa.x, fa.y, fb.x, fb.y);
}

__global__ void ncc_dpass(float* __restrict__ outp) {
    const int tid = blockIdx.x * blockDim.x + threadIdx.x;   // < 122880
    const int seg = tid / NCOLQ;
    const int cp = tid - seg * NCOLQ;
    const int wq = cp % (Wn / 4);
    int r = cp / (Wn / 4);
    const int h = r % Hn;
    const int b = r / Hn;
    const int d0 = seg * DSEGLEN;

    const size_t dS = (size_t)Hn * (Wn / 4);                 // slice stride (uint2)
    const size_t base = ((size_t)b * Dn) * dS + (size_t)h * (Wn / 4) + wq;
    const uint2* __restrict__ in = (const uint2*)g_hbuf;
    const size_t cNV = (size_t)NV / 4;                       // channel stride (uint2)

    float s[5][4];
    #pragma unroll
    for (int c = 0; c < 5; ++c)
        #pragma unroll
        for (int l = 0; l < 4; ++l) s[c][l] = 0.f;

    #pragma unroll
    for (int d = d0 - RW; d < d0 + RW; ++d) {
        if (d >= 0) {
            const size_t o = base + (size_t)d * dS;
            #pragma unroll
            for (int c = 0; c < 5; ++c) {
                const float4 v = cvt4(in[c * cNV + o]);
                s[c][0] += v.x; s[c][1] += v.y; s[c][2] += v.z; s[c][3] += v.w;
            }
        }
    }

    const float inv = 1.0f / WSZ;
    float acc = 0.f;
    #pragma unroll 2
    for (int dout = d0; dout < d0 + DSEGLEN; ++dout) {
        if (dout + RW < Dn) {
            const size_t o = base + (size_t)(dout + RW) * dS;
            #pragma unroll
            for (int c = 0; c < 5; ++c) {
                const float4 v = cvt4(in[c * cNV + o]);
                s[c][0] += v.x; s[c][1] += v.y; s[c][2] += v.z; s[c][3] += v.w;
            }
        }
        #pragma unroll
        for (int l = 0; l < 4; ++l) {
            const float uI = s[0][l] * inv, uJ = s[1][l] * inv;
            const float cross = s[4][l] - uJ * s[0][l] - uI * s[1][l] + uI * uJ * WSZ;
            const float Iv = s[2][l] - 2.f * uI * s[0][l] + uI * uI * WSZ;
            const float Jv = s[3][l] - 2.f * uJ * s[1][l] + uJ * uJ * WSZ;
            acc += cross * cross / (Iv * Jv + 1e-5f);
        }
        if (dout - RW >= 0) {
            const size_t o = base + (size_t)(dout - RW) * dS;
            #pragma unroll
            for (int c = 0; c < 5; ++c) {
                const float4 v = cvt4(in[c * cNV + o]);
                s[c][0] -= v.x; s[c][1] -= v.y; s[c][2] -= v.z; s[c][3] -= v.w;
            }
        }
    }

    __shared__ float red[128];
    red[threadIdx.x] = acc;
    __syncthreads();
    #pragma unroll
    for (int st = 64; st > 0; st >>= 1) {
        if (threadIdx.x < st) red[threadIdx.x] += red[threadIdx.x + st];
        __syncthreads();
    }

    __shared__ bool is_last;
    if (threadIdx.x == 0) {
        g_part[blockIdx.x] = red[0];
        __threadfence();
        unsigned old = atomicInc(&g_cnt, DPB - 1);
        is_last = (old == DPB - 1);
    }
    __syncthreads();

    if (is_last) {
        const volatile float* vp = g_part;
        double v = 0.0;
        for (int i = threadIdx.x; i < DPB; i += 128) v += (double)vp[i];
        __shared__ double dred[128];
        dred[threadIdx.x] = v;
        __syncthreads();
        #pragma unroll
        for (int st = 64; st > 0; st >>= 1) {
            if (threadIdx.x < st) dred[threadIdx.x] += dred[threadIdx.x + st];
            __syncthreads();
        }
        if (threadIdx.x == 0) outp[0] = (float)(-(dred[0] / (double)NV));
    }
}

extern "C" void kernel_launch(void* const* d_in, const int* in_sizes, int n_in,
                              void* d_out, int out_size) {
    const float* I = (const float*)d_in[0];
    const float* J = (const float*)d_in[1];
    float* out = (float*)d_out;

    cudaFuncSetAttribute(ncc_fused, cudaFuncAttributeMaxDynamicSharedMemorySize,
                         SMEM_BYTES);

    ncc_fused<<<Bn * Dn * (Hn / TH), FT, SMEM_BYTES>>>(I, J);  // 3840 blocks
    ncc_dpass<<<DPB, 128>>>(out);                               // 960 blocks
}

// round 9
// speedup vs baseline: 1.1656x; 1.0023x over previous
#include <cuda_runtime.h>
#include <cuda_fp16.h>

// Shape: [B=2, C=1, D=160, H=192, W=160] fp32, WIN=9 (radius 4), SAME zero pad.
#define Bn 2
#define Dn 160
#define Hn 192
#define Wn 160
#define NV (Bn*Dn*Hn*Wn)            // 9,830,400
#define RW 4
#define WSZ 729.0f

// Fused W+H pass tiling: TH=16, 384 threads, 3 blocks/SM @ 70.1 KB smem.
#define TH 16                        // output rows per block
#define ROWS (TH + 2*RW)             // 24 input rows with halo
#define ISTR 164                     // I/J smem stride (float4-aligned)
#define SSTRH 161                    // W-sum smem stride in halfs (odd)
#define SM_IJ (ROWS * ISTR)          // one input plane (floats)
#define SM_SH (ROWS * SSTRH)         // one W-sum plane (halfs)
#define SMEM_BYTES (2 * SM_IJ * 4 + 5 * SM_SH * 2)   // 70,128 B
#define FT 384                       // fused block threads

// D-pass: 4 columns/thread (uint2), 8 D-segments (40% halo), 128-thr blocks.
#define NCOLQ (Bn*Hn*(Wn/4))         // 15,360 column-quads
#define DSEG 8
#define DSEGLEN (Dn/DSEG)            // 20
#define DPB ((NCOLQ*DSEG)/128)       // 960 blocks

// Intermediate buffer in fp16, channel-major [c][b][d][h][w]. ~98.3 MB.
__device__ __align__(16) __half g_hbuf[5ll * NV];
__device__ float g_part[DPB];
__device__ unsigned g_cnt = 0;       // wraps -> graph-replay safe

// ---------------------------------------------------------------------------
// Fused W+H pass: stage I,J -> W window-sums (products on the fly, fp16
// scratch) -> H window-sum -> fp16 gmem.  384 threads/block, 3840 blocks.
// ---------------------------------------------------------------------------
__global__ __launch_bounds__(FT, 3)
void ncc_fused(const float* __restrict__ I, const float* __restrict__ J) {
    extern __shared__ char smraw[];
    float* __restrict__ sI = (float*)smraw;                  // [ROWS][ISTR]
    float* __restrict__ sJ = sI + SM_IJ;                     // [ROWS][ISTR]
    __half* __restrict__ sS = (__half*)(sJ + SM_IJ);         // [5][ROWS][SSTRH]

    const int t = threadIdx.x;
    const int tile = blockIdx.x;
    const int ht = tile % (Hn / TH);       // 12 tiles along H
    const int slice = tile / (Hn / TH);
    const int d = slice % Dn;
    const int b = slice / Dn;
    const int h0 = ht * TH;

    // Phase A: float4 loads of I,J rows [h0-4, h0+TH+4) into smem.
    for (int idx = t; idx < ROWS * (Wn / 4); idx += FT) {
        const int r = idx / (Wn / 4);
        const int wq = (idx - r * (Wn / 4)) * 4;
        const int hg = h0 - RW + r;
        float4 a = make_float4(0.f, 0.f, 0.f, 0.f);
        float4 c = a;
        if (hg >= 0 && hg < Hn) {
            const size_t o = ((size_t)(b * Dn + d) * Hn + hg) * Wn + wq;
            a = *(const float4*)(I + o);
            c = *(const float4*)(J + o);
        }
        *(float4*)(sI + r * ISTR + wq) = a;
        *(float4*)(sJ + r * ISTR + wq) = c;
    }
    __syncthreads();

    // Phase B: W window-sums for all 5 channels (products on the fly, fp32
    // running sums, fp16 stores). 24 rows x 16 chunks of 10 = 384 jobs.
    {
        const int row = t >> 4;
        const int c0 = (t & 15) * 10;
        const float* __restrict__ rI = sI + row * ISTR;
        const float* __restrict__ rJ = sJ + row * ISTR;
        float s0 = 0.f, s1 = 0.f, s2 = 0.f, s3 = 0.f, s4 = 0.f;
        #pragma unroll
        for (int k = c0 - RW; k <= c0 + RW; ++k) {
            if (k >= 0 && k < Wn) {
                const float a = rI[k], c = rJ[k];
                s0 += a; s1 += c; s2 += a * a; s3 += c * c; s4 += a * c;
            }
        }
        #pragma unroll
        for (int i = 0; i < 10; ++i) {
            const int w = c0 + i;
            sS[0 * SM_SH + row * SSTRH + w] = __float2half_rn(s0);
            sS[1 * SM_SH + row * SSTRH + w] = __float2half_rn(s1);
            sS[2 * SM_SH + row * SSTRH + w] = __float2half_rn(s2);
            sS[3 * SM_SH + row * SSTRH + w] = __float2half_rn(s3);
            sS[4 * SM_SH + row * SSTRH + w] = __float2half_rn(s4);
            if (w + RW + 1 < Wn) {
                const float a = rI[w + RW + 1], c = rJ[w + RW + 1];
                s0 += a; s1 += c; s2 += a * a; s3 += c * c; s4 += a * c;
            }
            if (w - RW >= 0) {
                const float a = rI[w - RW], c = rJ[w - RW];
                s0 -= a; s1 -= c; s2 -= a * a; s3 -= c * c; s4 -= a * c;
            }
        }
    }
    __syncthreads();

    // Phase C: H window-sum per (ch, w) column (fp32 running over fp16 taps).
    for (int job = t; job < 5 * Wn; job += FT) {
        const int w = job % Wn;
        const int ch = job / Wn;
        const __half* __restrict__ col = sS + ch * SM_SH + w;
        float s = 0.f;
        #pragma unroll
        for (int r = 0; r < 2 * RW; ++r) s += __half2float(col[r * SSTRH]);
        __half* __restrict__ ob = g_hbuf + (size_t)ch * NV +
                                  ((size_t)(b * Dn + d) * Hn + h0) * Wn + w;
        #pragma unroll
        for (int o = 0; o < TH; ++o) {
            s += __half2float(col[(o + 2 * RW) * SSTRH]);
            ob[(size_t)o * Wn] = __float2half_rn(s);
            s -= __half2float(col[o * SSTRH]);
        }
    }
}

// ---------------------------------------------------------------------------
// D-pass: running D window-sum (4 columns/thread via LDG.64) + cc +
// reduction + last-block finalize. 960 blocks x 128 threads, 8 segs of 20.
// ---------------------------------------------------------------------------
__device__ __forceinline__ float4 cvt4(uint2 v) {
    const float2 fa = __half22float2(*reinterpret_cast<__half2*>(&v.x));
    const float2 fb = __half22float2(*reinterpret_cast<__half2*>(&v.y));
    return make_float4(fa.x, fa.y, fb.x, fb.y);
}

__global__ void ncc_dpass(float* __restrict__ outp) {
    const int tid = blockIdx.x * blockDim.x + threadIdx.x;   // < 122880
    const int seg = tid / NCOLQ;
    const int cp = tid - seg * NCOLQ;
    const int wq = cp % (Wn / 4);
    int r = cp / (Wn / 4);
    const int h = r % Hn;
    const int b = r / Hn;
    const int d0 = seg * DSEGLEN;

    const size_t dS = (size_t)Hn * (Wn / 4);                 // slice stride (uint2)
    const size_t base = ((size_t)b * Dn) * dS + (size_t)h * (Wn / 4) + wq;
    const uint2* __restrict__ in = (const uint2*)g_hbuf;
    const size_t cNV = (size_t)NV / 4;                       // channel stride (uint2)

    float s[5][4];
    #pragma unroll
    for (int c = 0; c < 5; ++c)
        #pragma unroll
        for (int l = 0; l < 4; ++l) s[c][l] = 0.f;

    #pragma unroll
    for (int d = d0 - RW; d < d0 + RW; ++d) {
        if (d >= 0) {
            const size_t o = base + (size_t)d * dS;
            #pragma unroll
            for (int c = 0; c < 5; ++c) {
                const float4 v = cvt4(in[c * cNV + o]);
                s[c][0] += v.x; s[c][1] += v.y; s[c][2] += v.z; s[c][3] += v.w;
            }
        }
    }

    const float inv = 1.0f / WSZ;
    float acc = 0.f;
    #pragma unroll 2
    for (int dout = d0; dout < d0 + DSEGLEN; ++dout) {
        if (dout + RW < Dn) {
            const size_t o = base + (size_t)(dout + RW) * dS;
            #pragma unroll
            for (int c = 0; c < 5; ++c) {
                const float4 v = cvt4(in[c * cNV + o]);
                s[c][0] += v.x; s[c][1] += v.y; s[c][2] += v.z; s[c][3] += v.w;
            }
        }
        #pragma unroll
        for (int l = 0; l < 4; ++l) {
            const float uI = s[0][l] * inv, uJ = s[1][l] * inv;
            const float cross = s[4][l] - uJ * s[0][l] - uI * s[1][l] + uI * uJ * WSZ;
            const float Iv = s[2][l] - 2.f * uI * s[0][l] + uI * uI * WSZ;
            const float Jv = s[3][l] - 2.f * uJ * s[1][l] + uJ * uJ * WSZ;
            acc += cross * cross / (Iv * Jv + 1e-5f);
        }
        if (dout - RW >= 0) {
            const size_t o = base + (size_t)(dout - RW) * dS;
            #pragma unroll
            for (int c = 0; c < 5; ++c) {
                const float4 v = cvt4(in[c * cNV + o]);
                s[c][0] -= v.x; s[c][1] -= v.y; s[c][2] -= v.z; s[c][3] -= v.w;
            }
        }
    }

    __shared__ float red[128];
    red[threadIdx.x] = acc;
    __syncthreads();
    #pragma unroll
    for (int st = 64; st > 0; st >>= 1) {
        if (threadIdx.x < st) red[threadIdx.x] += red[threadIdx.x + st];
        __syncthreads();
    }

    __shared__ bool is_last;
    if (threadIdx.x == 0) {
        g_part[blockIdx.x] = red[0];
        __threadfence();
        unsigned old = atomicInc(&g_cnt, DPB - 1);
        is_last = (old == DPB - 1);
    }
    __syncthreads();

    if (is_last) {
        const volatile float* vp = g_part;
        double v = 0.0;
        for (int i = threadIdx.x; i < DPB; i += 128) v += (double)vp[i];
        __shared__ double dred[128];
        dred[threadIdx.x] = v;
        __syncthreads();
        #pragma unroll
        for (int st = 64; st > 0; st >>= 1) {
            if (threadIdx.x < st) dred[threadIdx.x] += dred[threadIdx.x + st];
            __syncthreads();
        }
        if (threadIdx.x == 0) outp[0] = (float)(-(dred[0] / (double)NV));
    }
}

extern "C" void kernel_launch(void* const* d_in, const int* in_sizes, int n_in,
                              void* d_out, int out_size) {
    const float* I = (const float*)d_in[0];
    const float* J = (const float*)d_in[1];
    float* out = (float*)d_out;

    cudaFuncSetAttribute(ncc_fused, cudaFuncAttributeMaxDynamicSharedMemorySize,
                         SMEM_BYTES);

    ncc_fused<<<Bn * Dn * (Hn / TH), FT, SMEM_BYTES>>>(I, J);  // 3840 blocks
    ncc_dpass<<<DPB, 128>>>(out);                               // 960 blocks
}

// round 10
// speedup vs baseline: 1.1720x; 1.0054x over previous
#include <cuda_runtime.h>
#include <cuda_fp16.h>

// Shape: [B=2, C=1, D=160, H=192, W=160] fp32, WIN=9 (radius 4), SAME zero pad.
#define Bn 2
#define Dn 160
#define Hn 192
#define Wn 160
#define NV (Bn*Dn*Hn*Wn)            // 9,830,400
#define RW 4
#define WSZ 729.0f

// Fused W+H pass tiling: TH=16, 384 threads, 3 blocks/SM @ 70.1 KB smem.
#define TH 16                        // output rows per block
#define ROWS (TH + 2*RW)             // 24 input rows with halo
#define ISTR 164                     // I/J smem stride (float4-aligned)
#define SSTRH 161                    // W-sum smem stride in halfs (odd)
#define SM_IJ (ROWS * ISTR)          // one input plane (floats)
#define SM_SH (ROWS * SSTRH)         // one W-sum plane (halfs)
#define SMEM_BYTES (2 * SM_IJ * 4 + 5 * SM_SH * 2)   // 70,128 B
#define FT 384                       // fused block threads

// D-pass: 4 columns/thread (uint2), 8 D-segments (40% halo), 128-thr blocks.
#define NCOLQ (Bn*Hn*(Wn/4))         // 15,360 column-quads
#define DSEG 8
#define DSEGLEN (Dn/DSEG)            // 20
#define DPB ((NCOLQ*DSEG)/128)       // 960 blocks

// Intermediate buffer in fp16, channel-major [c][b][d][h][w]. ~98.3 MB.
__device__ __align__(16) __half g_hbuf[5ll * NV];
__device__ float g_part[DPB];
__device__ unsigned g_cnt = 0;       // wraps -> graph-replay safe

// ---------------------------------------------------------------------------
// Fused W+H pass: stage I,J -> W window-sums (products on the fly, fp16
// scratch) -> H window-sum -> fp16 gmem.  384 threads/block, 3840 blocks.
// ---------------------------------------------------------------------------
__global__ __launch_bounds__(FT, 3)
void ncc_fused(const float* __restrict__ I, const float* __restrict__ J) {
    extern __shared__ char smraw[];
    float* __restrict__ sI = (float*)smraw;                  // [ROWS][ISTR]
    float* __restrict__ sJ = sI + SM_IJ;                     // [ROWS][ISTR]
    __half* __restrict__ sS = (__half*)(sJ + SM_IJ);         // [5][ROWS][SSTRH]

    const int t = threadIdx.x;
    const int tile = blockIdx.x;
    const int ht = tile % (Hn / TH);       // 12 tiles along H
    const int slice = tile / (Hn / TH);
    const int d = slice % Dn;
    const int b = slice / Dn;
    const int h0 = ht * TH;

    // Phase A: float4 loads of I,J rows [h0-4, h0+TH+4) into smem.
    for (int idx = t; idx < ROWS * (Wn / 4); idx += FT) {
        const int r = idx / (Wn / 4);
        const int wq = (idx - r * (Wn / 4)) * 4;
        const int hg = h0 - RW + r;
        float4 a = make_float4(0.f, 0.f, 0.f, 0.f);
        float4 c = a;
        if (hg >= 0 && hg < Hn) {
            const size_t o = ((size_t)(b * Dn + d) * Hn + hg) * Wn + wq;
            a = *(const float4*)(I + o);
            c = *(const float4*)(J + o);
        }
        *(float4*)(sI + r * ISTR + wq) = a;
        *(float4*)(sJ + r * ISTR + wq) = c;
    }
    __syncthreads();

    // Phase B: W window-sums for all 5 channels (products on the fly, fp32
    // running sums, fp16 stores). 24 rows x 16 chunks of 10 = 384 jobs.
    {
        const int row = t >> 4;
        const int c0 = (t & 15) * 10;
        const float* __restrict__ rI = sI + row * ISTR;
        const float* __restrict__ rJ = sJ + row * ISTR;
        float s0 = 0.f, s1 = 0.f, s2 = 0.f, s3 = 0.f, s4 = 0.f;
        #pragma unroll
        for (int k = c0 - RW; k <= c0 + RW; ++k) {
            if (k >= 0 && k < Wn) {
                const float a = rI[k], c = rJ[k];
                s0 += a; s1 += c; s2 += a * a; s3 += c * c; s4 += a * c;
            }
        }
        #pragma unroll
        for (int i = 0; i < 10; ++i) {
            const int w = c0 + i;
            sS[0 * SM_SH + row * SSTRH + w] = __float2half_rn(s0);
            sS[1 * SM_SH + row * SSTRH + w] = __float2half_rn(s1);
            sS[2 * SM_SH + row * SSTRH + w] = __float2half_rn(s2);
            sS[3 * SM_SH + row * SSTRH + w] = __float2half_rn(s3);
            sS[4 * SM_SH + row * SSTRH + w] = __float2half_rn(s4);
            if (w + RW + 1 < Wn) {
                const float a = rI[w + RW + 1], c = rJ[w + RW + 1];
                s0 += a; s1 += c; s2 += a * a; s3 += c * c; s4 += a * c;
            }
            if (w - RW >= 0) {
                const float a = rI[w - RW], c = rJ[w - RW];
                s0 -= a; s1 -= c; s2 -= a * a; s3 -= c * c; s4 -= a * c;
            }
        }
    }
    __syncthreads();

    // Phase C: H window-sum per (ch, w) column (fp32 running over fp16 taps).
    for (int job = t; job < 5 * Wn; job += FT) {
        const int w = job % Wn;
        const int ch = job / Wn;
        const __half* __restrict__ col = sS + ch * SM_SH + w;
        float s = 0.f;
        #pragma unroll
        for (int r = 0; r < 2 * RW; ++r) s += __half2float(col[r * SSTRH]);
        __half* __restrict__ ob = g_hbuf + (size_t)ch * NV +
                                  ((size_t)(b * Dn + d) * Hn + h0) * Wn + w;
        #pragma unroll
        for (int o = 0; o < TH; ++o) {
            s += __half2float(col[(o + 2 * RW) * SSTRH]);
            ob[(size_t)o * Wn] = __float2half_rn(s);
            s -= __half2float(col[o * SSTRH]);
        }
    }
}

// ---------------------------------------------------------------------------
// D-pass: running D window-sum (4 columns/thread via LDG.64) + cc +
// reduction + last-block finalize. 960 blocks x 128 threads, 8 segs of 20.
// ---------------------------------------------------------------------------
__device__ __forceinline__ float4 cvt4(uint2 v) {
    const float2 fa = __half22float2(*reinterpret_cast<__half2*>(&v.x));
    const float2 fb = __half22float2(*reinterpret_cast<__half2*>(&v.y));
    return make_float4(fa.x, fa.y, fb.x, fb.y);
}

__global__ void ncc_dpass(float* __restrict__ outp) {
    const int tid = blockIdx.x * blockDim.x + threadIdx.x;   // < 122880
    const int seg = tid / NCOLQ;
    const int cp = tid - seg * NCOLQ;
    const int wq = cp % (Wn / 4);
    int r = cp / (Wn / 4);
    const int h = r % Hn;
    const int b = r / Hn;
    const int d0 = seg * DSEGLEN;

    const size_t dS = (size_t)Hn * (Wn / 4);                 // slice stride (uint2)
    const size_t base = ((size_t)b * Dn) * dS + (size_t)h * (Wn / 4) + wq;
    const uint2* __restrict__ in = (const uint2*)g_hbuf;
    const size_t cNV = (size_t)NV / 4;                       // channel stride (uint2)

    float s[5][4];
    #pragma unroll
    for (int c = 0; c < 5; ++c)
        #pragma unroll
        for (int l = 0; l < 4; ++l) s[c][l] = 0.f;

    #pragma unroll
    for (int d = d0 - RW; d < d0 + RW; ++d) {
        if (d >= 0) {
            const size_t o = base + (size_t)d * dS;
            #pragma unroll
            for (int c = 0; c < 5; ++c) {
                const float4 v = cvt4(in[c * cNV + o]);
                s[c][0] += v.x; s[c][1] += v.y; s[c][2] += v.z; s[c][3] += v.w;
            }
        }
    }

    const float inv = 1.0f / WSZ;
    float acc = 0.f;
    #pragma unroll 2
    for (int dout = d0; dout < d0 + DSEGLEN; ++dout) {
        if (dout + RW < Dn) {
            const size_t o = base + (size_t)(dout + RW) * dS;
            #pragma unroll
            for (int c = 0; c < 5; ++c) {
                const float4 v = cvt4(in[c * cNV + o]);
                s[c][0] += v.x; s[c][1] += v.y; s[c][2] += v.z; s[c][3] += v.w;
            }
        }
        #pragma unroll
        for (int l = 0; l < 4; ++l) {
            const float uI = s[0][l] * inv, uJ = s[1][l] * inv;
            const float cross = s[4][l] - uJ * s[0][l] - uI * s[1][l] + uI * uJ * WSZ;
            const float Iv = s[2][l] - 2.f * uI * s[0][l] + uI * uI * WSZ;
            const float Jv = s[3][l] - 2.f * uJ * s[1][l] + uJ * uJ * WSZ;
            acc += cross * cross / (Iv * Jv + 1e-5f);
        }
        if (dout - RW >= 0) {
            const size_t o = base + (size_t)(dout - RW) * dS;
            #pragma unroll
            for (int c = 0; c < 5; ++c) {
                const float4 v = cvt4(in[c * cNV + o]);
                s[c][0] -= v.x; s[c][1] -= v.y; s[c][2] -= v.z; s[c][3] -= v.w;
            }
        }
    }

    __shared__ float red[128];
    red[threadIdx.x] = acc;
    __syncthreads();
    #pragma unroll
    for (int st = 64; st > 0; st >>= 1) {
        if (threadIdx.x < st) red[threadIdx.x] += red[threadIdx.x + st];
        __syncthreads();
    }

    __shared__ bool is_last;
    if (threadIdx.x == 0) {
        g_part[blockIdx.x] = red[0];
        __threadfence();
        unsigned old = atomicInc(&g_cnt, DPB - 1);
        is_last = (old == DPB - 1);
    }
    __syncthreads();

    if (is_last) {
        const volatile float* vp = g_part;
        double v = 0.0;
        for (int i = threadIdx.x; i < DPB; i += 128) v += (double)vp[i];
        __shared__ double dred[128];
        dred[threadIdx.x] = v;
        __syncthreads();
        #pragma unroll
        for (int st = 64; st > 0; st >>= 1) {
            if (threadIdx.x < st) dred[threadIdx.x] += dred[threadIdx.x + st];
            __syncthreads();
        }
        if (threadIdx.x == 0) outp[0] = (float)(-(dred[0] / (double)NV));
    }
}

extern "C" void kernel_launch(void* const* d_in, const int* in_sizes, int n_in,
                              void* d_out, int out_size) {
    const float* I = (const float*)d_in[0];
    const float* J = (const float*)d_in[1];
    float* out = (float*)d_out;

    cudaFuncSetAttribute(ncc_fused, cudaFuncAttributeMaxDynamicSharedMemorySize,
                         SMEM_BYTES);

    ncc_fused<<<Bn * Dn * (Hn / TH), FT, SMEM_BYTES>>>(I, J);  // 3840 blocks
    ncc_dpass<<<DPB, 128>>>(out);                               // 960 blocks
}